// round 1
// baseline (speedup 1.0000x reference)
#include <cuda_runtime.h>
#include <cuda_bf16.h>
#include <math.h>

// Problem constants
#define Bz 4
#define Nn 4096
#define DM 1024
#define Hh 16
#define DEPTH 64
#define ROWS (Bz * Nn)          // 16384
#define BH (Bz * Hh)            // 64
#define NSEG 8                  // segments for KtQ partial sums
#define SEG_ROWS (Nn / NSEG)    // 512

// ---------------------------------------------------------------------------
// Scratch (device globals; no allocation allowed)
// ---------------------------------------------------------------------------
__device__ float g_Q[ROWS * DM];
__device__ float g_K[ROWS * DM];
__device__ float g_V[ROWS * DM];
__device__ float g_attn[ROWS * DM];   // V @ KtQ / Z, combined-head layout
__device__ float g_proj[ROWS * DM];   // attn @ Wo + bo
__device__ float g_KtQp[NSEG * BH * DEPTH * DEPTH]; // per-segment partials
__device__ float g_KtQ[BH * DEPTH * DEPTH];
__device__ float g_qsp[NSEG * BH * DEPTH];
__device__ float g_qs[BH * DEPTH];

// ---------------------------------------------------------------------------
// SGEMM: C[M,1024] = A[M,1024] @ W[1024,1024] + bias, optional elu(x)+1
// BM=128 BN=128 BK=16, 256 threads, 8x8 microtile
// grid: (DM/128, ROWS/128)
// ---------------------------------------------------------------------------
__global__ __launch_bounds__(256, 2)
void sgemm_k(const float* __restrict__ A, const float* __restrict__ W,
             const float* __restrict__ bias, float* __restrict__ C, int act)
{
    __shared__ float As[16][128];
    __shared__ float Bs[16][128];

    const int bm = blockIdx.y * 128;
    const int bn = blockIdx.x * 128;
    const int tid = threadIdx.x;
    const int tx = tid & 15;       // 0..15 -> n microtile
    const int ty = tid >> 4;       // 0..15 -> m microtile

    float acc[8][8];
#pragma unroll
    for (int i = 0; i < 8; ++i)
#pragma unroll
        for (int j = 0; j < 8; ++j) acc[i][j] = 0.0f;

    for (int k0 = 0; k0 < DM; k0 += 16) {
#pragma unroll
        for (int p = 0; p < 2; ++p) {
            int i = tid + p * 256;
            // A tile: 128 rows x 16 cols = 512 float4 (4 f4 per row)
            int ar = i >> 2, ac = (i & 3) * 4;
            float4 va = *(const float4*)&A[(size_t)(bm + ar) * DM + k0 + ac];
            As[ac + 0][ar] = va.x;
            As[ac + 1][ar] = va.y;
            As[ac + 2][ar] = va.z;
            As[ac + 3][ar] = va.w;
            // B tile: 16 rows x 128 cols = 512 float4 (32 f4 per row)
            int br = i >> 5, bc = (i & 31) * 4;
            *(float4*)&Bs[br][bc] = *(const float4*)&W[(size_t)(k0 + br) * DM + bn + bc];
        }
        __syncthreads();

#pragma unroll
        for (int kk = 0; kk < 16; ++kk) {
            float ra[8], rb[8];
            *(float4*)(ra)     = *(const float4*)&As[kk][ty * 8];
            *(float4*)(ra + 4) = *(const float4*)&As[kk][ty * 8 + 4];
            *(float4*)(rb)     = *(const float4*)&Bs[kk][tx * 8];
            *(float4*)(rb + 4) = *(const float4*)&Bs[kk][tx * 8 + 4];
#pragma unroll
            for (int i = 0; i < 8; ++i)
#pragma unroll
                for (int j = 0; j < 8; ++j)
                    acc[i][j] = fmaf(ra[i], rb[j], acc[i][j]);
        }
        __syncthreads();
    }

    // epilogue
#pragma unroll
    for (int i = 0; i < 8; ++i) {
        int row = bm + ty * 8 + i;
#pragma unroll
        for (int j4 = 0; j4 < 2; ++j4) {
            int col = bn + tx * 8 + j4 * 4;
            float4 o;
            float* op = &o.x;
#pragma unroll
            for (int j = 0; j < 4; ++j) {
                float v = acc[i][j4 * 4 + j] + bias[col + j];
                if (act == 1) v = (v > 0.0f) ? (v + 1.0f) : expf(v);
                op[j] = v;
            }
            *(float4*)&C[(size_t)row * DM + col] = o;
        }
    }
}

// ---------------------------------------------------------------------------
// Per-(b,h) KtQ[d][e] = sum_l K[l,d]*Q[l,e] and qsum[e] = sum_l Q[l,e]
// grid (BH, NSEG), 256 threads, 4x4 microtile over 64x64.
// Writes per-segment partials (deterministic; no atomics).
// ---------------------------------------------------------------------------
__global__ __launch_bounds__(256)
void ktq_k()
{
    __shared__ float Ks[16][64];
    __shared__ float Qs[16][64];

    const int bh = blockIdx.x;
    const int b = bh >> 4, h = bh & 15;
    const int seg = blockIdx.y;
    const int tid = threadIdx.x;
    const int tx = tid & 15;   // e group
    const int ty = tid >> 4;   // d group
    const int ldrow = tid >> 4;            // load: row 0..15
    const int ldc4  = (tid & 15) * 4;      // load: col (float4)

    float acc[4][4];
#pragma unroll
    for (int i = 0; i < 4; ++i)
#pragma unroll
        for (int j = 0; j < 4; ++j) acc[i][j] = 0.0f;
    float qsv = 0.0f;

    const size_t hb = (size_t)h * DEPTH;

    for (int ch = 0; ch < SEG_ROWS / 16; ++ch) {
        int n0 = seg * SEG_ROWS + ch * 16;
        size_t gbase = ((size_t)(b * Nn + n0 + ldrow)) * DM + hb + ldc4;
        *(float4*)&Ks[ldrow][ldc4] = *(const float4*)&g_K[gbase];
        *(float4*)&Qs[ldrow][ldc4] = *(const float4*)&g_Q[gbase];
        __syncthreads();

#pragma unroll
        for (int l = 0; l < 16; ++l) {
            float ra[4], rb[4];
            *(float4*)ra = *(const float4*)&Ks[l][ty * 4];
            *(float4*)rb = *(const float4*)&Qs[l][tx * 4];
#pragma unroll
            for (int i = 0; i < 4; ++i)
#pragma unroll
                for (int j = 0; j < 4; ++j)
                    acc[i][j] = fmaf(ra[i], rb[j], acc[i][j]);
        }
        if (tid < 64) {
#pragma unroll
            for (int l = 0; l < 16; ++l) qsv += Qs[l][tid];
        }
        __syncthreads();
    }

    float* outp = &g_KtQp[((size_t)seg * BH + bh) * (DEPTH * DEPTH)];
#pragma unroll
    for (int i = 0; i < 4; ++i)
#pragma unroll
        for (int j = 0; j < 4; ++j)
            outp[(ty * 4 + i) * DEPTH + tx * 4 + j] = acc[i][j];

    if (tid < 64)
        g_qsp[((size_t)seg * BH + bh) * DEPTH + tid] = qsv;
}

// Deterministic reductions of the per-segment partials.
__global__ void red_ktq_k()
{
    int i = blockIdx.x * 256 + threadIdx.x;
    if (i < BH * DEPTH * DEPTH) {
        float s = 0.0f;
#pragma unroll
        for (int seg = 0; seg < NSEG; ++seg)
            s += g_KtQp[seg * (BH * DEPTH * DEPTH) + i];
        g_KtQ[i] = s;
    }
}
__global__ void red_qs_k()
{
    int i = blockIdx.x * 256 + threadIdx.x;
    if (i < BH * DEPTH) {
        float s = 0.0f;
#pragma unroll
        for (int seg = 0; seg < NSEG; ++seg)
            s += g_qsp[seg * (BH * DEPTH) + i];
        g_qs[i] = s;
    }
}

// ---------------------------------------------------------------------------
// out[m,e] = (sum_d V[m,d]*KtQ[d,e]) / (K[m,:].qsum + 1e-9)
// grid (BH, Nn/64), block (64, 8): 64 rows per block, 8 rows per iteration.
// ---------------------------------------------------------------------------
__global__ __launch_bounds__(512)
void out_k()
{
    __shared__ float S[DEPTH * DEPTH];   // KtQ for this bh
    __shared__ float qs[DEPTH];
    __shared__ float Vs[8][DEPTH];
    __shared__ float Ks2[8][DEPTH];

    const int bh = blockIdx.x;
    const int b = bh >> 4, h = bh & 15;
    const int rowbase = blockIdx.y * 64;
    const int tx = threadIdx.x;  // 0..63 = e
    const int ty = threadIdx.y;  // 0..7
    const int tid = ty * 64 + tx;

#pragma unroll
    for (int p = 0; p < 8; ++p)
        S[tid + p * 512] = g_KtQ[(size_t)bh * (DEPTH * DEPTH) + tid + p * 512];
    if (tid < DEPTH) qs[tid] = g_qs[(size_t)bh * DEPTH + tid];
    __syncthreads();

    const size_t hb = (size_t)h * DEPTH;

    for (int it = 0; it < 8; ++it) {
        int row = rowbase + it * 8 + ty;
        size_t base = ((size_t)(b * Nn + row)) * DM + hb;
        Vs[ty][tx]  = g_V[base + tx];
        Ks2[ty][tx] = g_K[base + tx];
        __syncthreads();

        float z = 0.0f;
#pragma unroll
        for (int d = 0; d < DEPTH; ++d) z = fmaf(Ks2[ty][d], qs[d], z);
        float o = 0.0f;
#pragma unroll
        for (int d = 0; d < DEPTH; ++d) o = fmaf(Vs[ty][d], S[d * DEPTH + tx], o);

        g_attn[base + tx] = o / (z + 1e-9f);
        __syncthreads();
    }
}

// ---------------------------------------------------------------------------
// x = query + proj; LayerNorm(x)*gamma + beta. One block per row.
// ---------------------------------------------------------------------------
__global__ __launch_bounds__(256)
void ln_k(const float* __restrict__ resid, const float* __restrict__ gamma,
          const float* __restrict__ beta, float* __restrict__ out)
{
    __shared__ float red[256];
    const int row = blockIdx.x;
    const int tid = threadIdx.x;
    const float* a = g_proj + (size_t)row * DM;
    const float* r = resid + (size_t)row * DM;

    float x[4];
    float s = 0.0f;
#pragma unroll
    for (int j = 0; j < 4; ++j) {
        int c = tid + j * 256;
        x[j] = a[c] + r[c];
        s += x[j];
    }
    red[tid] = s;
    __syncthreads();
    for (int st = 128; st > 0; st >>= 1) {
        if (tid < st) red[tid] += red[tid + st];
        __syncthreads();
    }
    float mu = red[0] * (1.0f / 1024.0f);
    __syncthreads();

    float v = 0.0f;
#pragma unroll
    for (int j = 0; j < 4; ++j) {
        float d = x[j] - mu;
        v += d * d;
    }
    red[tid] = v;
    __syncthreads();
    for (int st = 128; st > 0; st >>= 1) {
        if (tid < st) red[tid] += red[tid + st];
        __syncthreads();
    }
    float inv = rsqrtf(red[0] * (1.0f / 1024.0f) + 1e-6f);

    float* o = out + (size_t)row * DM;
#pragma unroll
    for (int j = 0; j < 4; ++j) {
        int c = tid + j * 256;
        o[c] = (x[j] - mu) * inv * gamma[c] + beta[c];
    }
}

// ---------------------------------------------------------------------------
// Launch
// ---------------------------------------------------------------------------
extern "C" void kernel_launch(void* const* d_in, const int* in_sizes, int n_in,
                              void* d_out, int out_size)
{
    const float* query = (const float*)d_in[0];
    const float* key_  = (const float*)d_in[1];
    const float* value = (const float*)d_in[2];
    const float* Wq = (const float*)d_in[3];
    const float* bq = (const float*)d_in[4];
    const float* Wk = (const float*)d_in[5];
    const float* bk = (const float*)d_in[6];
    const float* Wv = (const float*)d_in[7];
    const float* bv = (const float*)d_in[8];
    const float* Wo = (const float*)d_in[9];
    const float* bo = (const float*)d_in[10];
    const float* gamma = (const float*)d_in[11];
    const float* beta  = (const float*)d_in[12];
    float* out = (float*)d_out;

    void *pQ, *pK, *pV, *pAttn, *pProj;
    cudaGetSymbolAddress(&pQ, g_Q);
    cudaGetSymbolAddress(&pK, g_K);
    cudaGetSymbolAddress(&pV, g_V);
    cudaGetSymbolAddress(&pAttn, g_attn);
    cudaGetSymbolAddress(&pProj, g_proj);

    dim3 ggrid(DM / 128, ROWS / 128);

    // Projections (elu+1 fused for Q and K)
    sgemm_k<<<ggrid, 256>>>(query, Wq, bq, (float*)pQ, 1);
    sgemm_k<<<ggrid, 256>>>(key_,  Wk, bk, (float*)pK, 1);
    sgemm_k<<<ggrid, 256>>>(value, Wv, bv, (float*)pV, 0);

    // KtQ + qsum partials, then deterministic reduce
    ktq_k<<<dim3(BH, NSEG), 256>>>();
    red_ktq_k<<<(BH * DEPTH * DEPTH + 255) / 256, 256>>>();
    red_qs_k<<<(BH * DEPTH + 255) / 256, 256>>>();

    // out = V @ KtQ / Z
    out_k<<<dim3(BH, Nn / 64), dim3(64, 8)>>>();

    // O projection
    sgemm_k<<<ggrid, 256>>>((const float*)pAttn, Wo, bo, (float*)pProj, 0);

    // residual + layernorm
    ln_k<<<ROWS, 256>>>(query, gamma, beta, out);
}

// round 3
// speedup vs baseline: 2.2685x; 2.2685x over previous
#include <cuda_runtime.h>
#include <cuda_bf16.h>
#include <math.h>

// Problem constants
#define Bz 4
#define Nn 4096
#define DM 1024
#define Hh 16
#define DEPTH 64
#define ROWS (Bz * Nn)          // 16384
#define BH (Bz * Hh)            // 64
#define NSEG 8
#define SEG_ROWS (Nn / NSEG)

// ---------------------------------------------------------------------------
// Scratch (device globals)
// ---------------------------------------------------------------------------
__device__ float g_Q[ROWS * DM];
__device__ float g_K[ROWS * DM];
__device__ float g_V[ROWS * DM];
__device__ float g_attn[ROWS * DM];
__device__ float g_proj[ROWS * DM];
__device__ float g_Wt[4 * DM * DM];     // transposed + tf32-rounded weights
__device__ float g_KtQp[NSEG * BH * DEPTH * DEPTH];
__device__ float g_KtQ[BH * DEPTH * DEPTH];
__device__ float g_qsp[NSEG * BH * DEPTH];
__device__ float g_qs[BH * DEPTH];

__device__ __forceinline__ float tf32r(float x) {
    float r;
    asm("cvt.rna.tf32.f32 %0, %1;" : "=f"(r) : "f"(x));
    return r;
}

// ---------------------------------------------------------------------------
// Weight transpose + tf32 rounding: Wt[n][k] = round_tf32(W[k][n])
// ---------------------------------------------------------------------------
__global__ void transpose_k(const float* __restrict__ W, float* __restrict__ Wt)
{
    __shared__ float t[32][33];
    const int bx = blockIdx.x * 32;   // n
    const int by = blockIdx.y * 32;   // k
    const int tx = threadIdx.x, ty = threadIdx.y;
#pragma unroll
    for (int i = 0; i < 32; i += 8)
        t[ty + i][tx] = W[(size_t)(by + ty + i) * DM + bx + tx];
    __syncthreads();
#pragma unroll
    for (int i = 0; i < 32; i += 8)
        Wt[(size_t)(bx + ty + i) * DM + by + tx] = tf32r(t[tx][ty + i]);
}

// ---------------------------------------------------------------------------
// tf32 mma.sync GEMM: C[M,1024] = A @ Wt^T + bias   (Wt is [N,K], pre-rounded)
// CTA tile 128x128x16, 8 warps in 2x4, warp tile 64x32 = 4x4 m16n8k8 tiles.
// Double-buffered smem (pad stride 20 floats), register-prefetch pipeline.
// grid (8, 128), 256 threads.
// ---------------------------------------------------------------------------
#define SSTRIDE 20

__device__ __forceinline__ void mma_tf32(float* d, const unsigned* a, const unsigned* b)
{
    asm volatile(
        "mma.sync.aligned.m16n8k8.row.col.f32.tf32.tf32.f32 "
        "{%0,%1,%2,%3}, {%4,%5,%6,%7}, {%8,%9}, {%0,%1,%2,%3};"
        : "+f"(d[0]), "+f"(d[1]), "+f"(d[2]), "+f"(d[3])
        : "r"(a[0]), "r"(a[1]), "r"(a[2]), "r"(a[3]), "r"(b[0]), "r"(b[1]));
}

__global__ __launch_bounds__(256, 2)
void gemm_mma_k(const float* __restrict__ A, const float* __restrict__ Bt,
                const float* __restrict__ bias, float* __restrict__ C, int act)
{
    __shared__ float As[2][128 * SSTRIDE];
    __shared__ float Bs[2][128 * SSTRIDE];

    const int tid = threadIdx.x;
    const int wid = tid >> 5, lane = tid & 31;
    const int gid = lane >> 2, tig = lane & 3;
    const int warpM = wid >> 2, warpN = wid & 3;     // 2 x 4
    const int bm = blockIdx.y * 128;
    const int bn = blockIdx.x * 128;

    // gmem load mapping: 2 threads per row, 8 floats (2 float4) each
    const int lr = tid >> 1;
    const int lc = (tid & 1) * 8;
    const float* aptr = A + (size_t)(bm + lr) * DM + lc;
    const float* bptr = Bt + (size_t)(bn + lr) * DM + lc;
    float* sAdst0 = &As[0][lr * SSTRIDE + lc];
    float* sBdst0 = &Bs[0][lr * SSTRIDE + lc];
    float* sAdst1 = &As[1][lr * SSTRIDE + lc];
    float* sBdst1 = &Bs[1][lr * SSTRIDE + lc];

    float acc[4][4][4];
#pragma unroll
    for (int i = 0; i < 4; ++i)
#pragma unroll
        for (int j = 0; j < 4; ++j)
#pragma unroll
            for (int q = 0; q < 4; ++q) acc[i][j][q] = 0.0f;

    float4 pa0, pa1, pb0, pb1;

    // prefetch tile 0 and store
    pa0 = *(const float4*)(aptr);
    pa1 = *(const float4*)(aptr + 4);
    pb0 = *(const float4*)(bptr);
    pb1 = *(const float4*)(bptr + 4);
    pa0.x = tf32r(pa0.x); pa0.y = tf32r(pa0.y); pa0.z = tf32r(pa0.z); pa0.w = tf32r(pa0.w);
    pa1.x = tf32r(pa1.x); pa1.y = tf32r(pa1.y); pa1.z = tf32r(pa1.z); pa1.w = tf32r(pa1.w);
    *(float4*)(sAdst0) = pa0;
    *(float4*)(sAdst0 + 4) = pa1;
    *(float4*)(sBdst0) = pb0;
    *(float4*)(sBdst0 + 4) = pb1;
    __syncthreads();

    for (int c = 0; c < 64; ++c) {
        const int s = c & 1;
        if (c < 63) {
            const float* ap = aptr + (c + 1) * 16;
            const float* bp = bptr + (c + 1) * 16;
            pa0 = *(const float4*)(ap);
            pa1 = *(const float4*)(ap + 4);
            pb0 = *(const float4*)(bp);
            pb1 = *(const float4*)(bp + 4);
        }

        const float* sa = As[s];
        const float* sb = Bs[s];
#pragma unroll
        for (int ks = 0; ks < 2; ++ks) {
            unsigned afr[4][4], bfr[4][2];
#pragma unroll
            for (int mt = 0; mt < 4; ++mt) {
                const float* p = sa + (warpM * 64 + mt * 16 + gid) * SSTRIDE + ks * 8 + tig;
                afr[mt][0] = __float_as_uint(p[0]);
                afr[mt][1] = __float_as_uint(p[8 * SSTRIDE]);
                afr[mt][2] = __float_as_uint(p[4]);
                afr[mt][3] = __float_as_uint(p[8 * SSTRIDE + 4]);
            }
#pragma unroll
            for (int nt = 0; nt < 4; ++nt) {
                const float* p = sb + (warpN * 32 + nt * 8 + gid) * SSTRIDE + ks * 8 + tig;
                bfr[nt][0] = __float_as_uint(p[0]);
                bfr[nt][1] = __float_as_uint(p[4]);
            }
#pragma unroll
            for (int mt = 0; mt < 4; ++mt)
#pragma unroll
                for (int nt = 0; nt < 4; ++nt)
                    mma_tf32(acc[mt][nt], afr[mt], bfr[nt]);
        }

        if (c < 63) {
            pa0.x = tf32r(pa0.x); pa0.y = tf32r(pa0.y); pa0.z = tf32r(pa0.z); pa0.w = tf32r(pa0.w);
            pa1.x = tf32r(pa1.x); pa1.y = tf32r(pa1.y); pa1.z = tf32r(pa1.z); pa1.w = tf32r(pa1.w);
            float* da = (s == 0) ? sAdst1 : sAdst0;
            float* db = (s == 0) ? sBdst1 : sBdst0;
            *(float4*)(da) = pa0;
            *(float4*)(da + 4) = pa1;
            *(float4*)(db) = pb0;
            *(float4*)(db + 4) = pb1;
        }
        __syncthreads();
    }

    // epilogue
#pragma unroll
    for (int mt = 0; mt < 4; ++mt) {
        const int r0 = bm + warpM * 64 + mt * 16 + gid;
#pragma unroll
        for (int nt = 0; nt < 4; ++nt) {
            const int cn = bn + warpN * 32 + nt * 8 + 2 * tig;
            const float b0 = bias[cn], b1 = bias[cn + 1];
            float v0 = acc[mt][nt][0] + b0;
            float v1 = acc[mt][nt][1] + b1;
            float v2 = acc[mt][nt][2] + b0;
            float v3 = acc[mt][nt][3] + b1;
            if (act == 1) {
                v0 = (v0 > 0.0f) ? (v0 + 1.0f) : expf(v0);
                v1 = (v1 > 0.0f) ? (v1 + 1.0f) : expf(v1);
                v2 = (v2 > 0.0f) ? (v2 + 1.0f) : expf(v2);
                v3 = (v3 > 0.0f) ? (v3 + 1.0f) : expf(v3);
            }
            *(float2*)&C[(size_t)r0 * DM + cn] = make_float2(v0, v1);
            *(float2*)&C[(size_t)(r0 + 8) * DM + cn] = make_float2(v2, v3);
        }
    }
}

// ---------------------------------------------------------------------------
// Per-(b,h) KtQ[d][e] = sum_l K[l,d]*Q[l,e] and qsum[e] = sum_l Q[l,e]
// ---------------------------------------------------------------------------
__global__ __launch_bounds__(256)
void ktq_k()
{
    __shared__ float Ks[16][64];
    __shared__ float Qs[16][64];

    const int bh = blockIdx.x;
    const int b = bh >> 4, h = bh & 15;
    const int seg = blockIdx.y;
    const int tid = threadIdx.x;
    const int tx = tid & 15;
    const int ty = tid >> 4;
    const int ldrow = tid >> 4;
    const int ldc4  = (tid & 15) * 4;

    float acc[4][4];
#pragma unroll
    for (int i = 0; i < 4; ++i)
#pragma unroll
        for (int j = 0; j < 4; ++j) acc[i][j] = 0.0f;
    float qsv = 0.0f;

    const size_t hb = (size_t)h * DEPTH;

    for (int ch = 0; ch < SEG_ROWS / 16; ++ch) {
        int n0 = seg * SEG_ROWS + ch * 16;
        size_t gbase = ((size_t)(b * Nn + n0 + ldrow)) * DM + hb + ldc4;
        *(float4*)&Ks[ldrow][ldc4] = *(const float4*)&g_K[gbase];
        *(float4*)&Qs[ldrow][ldc4] = *(const float4*)&g_Q[gbase];
        __syncthreads();

#pragma unroll
        for (int l = 0; l < 16; ++l) {
            float ra[4], rb[4];
            *(float4*)ra = *(const float4*)&Ks[l][ty * 4];
            *(float4*)rb = *(const float4*)&Qs[l][tx * 4];
#pragma unroll
            for (int i = 0; i < 4; ++i)
#pragma unroll
                for (int j = 0; j < 4; ++j)
                    acc[i][j] = fmaf(ra[i], rb[j], acc[i][j]);
        }
        if (tid < 64) {
#pragma unroll
            for (int l = 0; l < 16; ++l) qsv += Qs[l][tid];
        }
        __syncthreads();
    }

    float* outp = &g_KtQp[((size_t)seg * BH + bh) * (DEPTH * DEPTH)];
#pragma unroll
    for (int i = 0; i < 4; ++i)
#pragma unroll
        for (int j = 0; j < 4; ++j)
            outp[(ty * 4 + i) * DEPTH + tx * 4 + j] = acc[i][j];

    if (tid < 64)
        g_qsp[((size_t)seg * BH + bh) * DEPTH + tid] = qsv;
}

__global__ void red_ktq_k()
{
    int i = blockIdx.x * 256 + threadIdx.x;
    if (i < BH * DEPTH * DEPTH) {
        float s = 0.0f;
#pragma unroll
        for (int seg = 0; seg < NSEG; ++seg)
            s += g_KtQp[seg * (BH * DEPTH * DEPTH) + i];
        g_KtQ[i] = s;
    }
}
__global__ void red_qs_k()
{
    int i = blockIdx.x * 256 + threadIdx.x;
    if (i < BH * DEPTH) {
        float s = 0.0f;
#pragma unroll
        for (int seg = 0; seg < NSEG; ++seg)
            s += g_qsp[seg * (BH * DEPTH) + i];
        g_qs[i] = s;
    }
}

// ---------------------------------------------------------------------------
// out[m,e] = (sum_d V[m,d]*KtQ[d,e]) / (K[m,:].qsum + 1e-9)
// ---------------------------------------------------------------------------
__global__ __launch_bounds__(512)
void out_k()
{
    __shared__ float S[DEPTH * DEPTH];
    __shared__ float qs[DEPTH];
    __shared__ float Vs[8][DEPTH];
    __shared__ float Ks2[8][DEPTH];

    const int bh = blockIdx.x;
    const int b = bh >> 4, h = bh & 15;
    const int rowbase = blockIdx.y * 64;
    const int tx = threadIdx.x;
    const int ty = threadIdx.y;
    const int tid = ty * 64 + tx;

#pragma unroll
    for (int p = 0; p < 8; ++p)
        S[tid + p * 512] = g_KtQ[(size_t)bh * (DEPTH * DEPTH) + tid + p * 512];
    if (tid < DEPTH) qs[tid] = g_qs[(size_t)bh * DEPTH + tid];
    __syncthreads();

    const size_t hb = (size_t)h * DEPTH;

    for (int it = 0; it < 8; ++it) {
        int row = rowbase + it * 8 + ty;
        size_t base = ((size_t)(b * Nn + row)) * DM + hb;
        Vs[ty][tx]  = g_V[base + tx];
        Ks2[ty][tx] = g_K[base + tx];
        __syncthreads();

        float z = 0.0f;
#pragma unroll
        for (int d = 0; d < DEPTH; ++d) z = fmaf(Ks2[ty][d], qs[d], z);
        float o = 0.0f;
#pragma unroll
        for (int d = 0; d < DEPTH; ++d) o = fmaf(Vs[ty][d], S[d * DEPTH + tx], o);

        // round attn output to tf32 so the O-projection's A operand is exact
        g_attn[base + tx] = tf32r(o / (z + 1e-9f));
        __syncthreads();
    }
}

// ---------------------------------------------------------------------------
// x = query + proj; LayerNorm(x)*gamma + beta
// ---------------------------------------------------------------------------
__global__ __launch_bounds__(256)
void ln_k(const float* __restrict__ resid, const float* __restrict__ gamma,
          const float* __restrict__ beta, float* __restrict__ out)
{
    __shared__ float red[256];
    const int row = blockIdx.x;
    const int tid = threadIdx.x;
    const float* a = g_proj + (size_t)row * DM;
    const float* r = resid + (size_t)row * DM;

    float x[4];
    float s = 0.0f;
#pragma unroll
    for (int j = 0; j < 4; ++j) {
        int c = tid + j * 256;
        x[j] = a[c] + r[c];
        s += x[j];
    }
    red[tid] = s;
    __syncthreads();
    for (int st = 128; st > 0; st >>= 1) {
        if (tid < st) red[tid] += red[tid + st];
        __syncthreads();
    }
    float mu = red[0] * (1.0f / 1024.0f);
    __syncthreads();

    float v = 0.0f;
#pragma unroll
    for (int j = 0; j < 4; ++j) {
        float d = x[j] - mu;
        v += d * d;
    }
    red[tid] = v;
    __syncthreads();
    for (int st = 128; st > 0; st >>= 1) {
        if (tid < st) red[tid] += red[tid + st];
        __syncthreads();
    }
    float inv = rsqrtf(red[0] * (1.0f / 1024.0f) + 1e-6f);

    float* o = out + (size_t)row * DM;
#pragma unroll
    for (int j = 0; j < 4; ++j) {
        int c = tid + j * 256;
        o[c] = (x[j] - mu) * inv * gamma[c] + beta[c];
    }
}

// ---------------------------------------------------------------------------
// Launch
// ---------------------------------------------------------------------------
extern "C" void kernel_launch(void* const* d_in, const int* in_sizes, int n_in,
                              void* d_out, int out_size)
{
    const float* query = (const float*)d_in[0];
    const float* key_  = (const float*)d_in[1];
    const float* value = (const float*)d_in[2];
    const float* Wq = (const float*)d_in[3];
    const float* bq = (const float*)d_in[4];
    const float* Wk = (const float*)d_in[5];
    const float* bk = (const float*)d_in[6];
    const float* Wv = (const float*)d_in[7];
    const float* bv = (const float*)d_in[8];
    const float* Wo = (const float*)d_in[9];
    const float* bo = (const float*)d_in[10];
    const float* gamma = (const float*)d_in[11];
    const float* beta  = (const float*)d_in[12];
    float* out = (float*)d_out;

    void *pQ, *pK, *pV, *pAttn, *pProj, *pWt;
    cudaGetSymbolAddress(&pQ, g_Q);
    cudaGetSymbolAddress(&pK, g_K);
    cudaGetSymbolAddress(&pV, g_V);
    cudaGetSymbolAddress(&pAttn, g_attn);
    cudaGetSymbolAddress(&pProj, g_proj);
    cudaGetSymbolAddress(&pWt, g_Wt);
    float* Wt = (float*)pWt;

    // Transpose + tf32-round the 4 weight matrices
    dim3 tgrid(DM / 32, DM / 32), tblk(32, 8);
    transpose_k<<<tgrid, tblk>>>(Wq, Wt + 0 * DM * DM);
    transpose_k<<<tgrid, tblk>>>(Wk, Wt + 1 * DM * DM);
    transpose_k<<<tgrid, tblk>>>(Wv, Wt + 2 * DM * DM);
    transpose_k<<<tgrid, tblk>>>(Wo, Wt + 3 * DM * DM);

    dim3 ggrid(DM / 128, ROWS / 128);

    gemm_mma_k<<<ggrid, 256>>>(query, Wt + 0 * DM * DM, bq, (float*)pQ, 1);
    gemm_mma_k<<<ggrid, 256>>>(key_,  Wt + 1 * DM * DM, bk, (float*)pK, 1);
    gemm_mma_k<<<ggrid, 256>>>(value, Wt + 2 * DM * DM, bv, (float*)pV, 0);

    ktq_k<<<dim3(BH, NSEG), 256>>>();
    red_ktq_k<<<(BH * DEPTH * DEPTH + 255) / 256, 256>>>();
    red_qs_k<<<(BH * DEPTH + 255) / 256, 256>>>();

    out_k<<<dim3(BH, Nn / 64), dim3(64, 8)>>>();

    gemm_mma_k<<<ggrid, 256>>>((const float*)pAttn, Wt + 3 * DM * DM, bo, (float*)pProj, 0);

    ln_k<<<ROWS, 256>>>(query, gamma, beta, out);
}

// round 4
// speedup vs baseline: 2.3456x; 1.0340x over previous
#include <cuda_runtime.h>
#include <cuda_bf16.h>
#include <math.h>

// Problem constants
#define Bz 4
#define Nn 4096
#define DM 1024
#define Hh 16
#define DEPTH 64
#define ROWS (Bz * Nn)          // 16384
#define BH (Bz * Hh)            // 64
#define NSEG 8
#define SEG_ROWS (Nn / NSEG)

// ---------------------------------------------------------------------------
// Scratch (device globals)
// ---------------------------------------------------------------------------
__device__ float g_Q[ROWS * DM];
__device__ float g_K[ROWS * DM];
__device__ float g_V[ROWS * DM];
__device__ float g_attn[ROWS * DM];
__device__ float g_proj[ROWS * DM];
__device__ float g_Wt[4 * DM * DM];     // transposed + tf32-rounded weights
__device__ float g_KtQp[NSEG * BH * DEPTH * DEPTH];
__device__ float g_KtQ[BH * DEPTH * DEPTH];
__device__ float g_qsp[NSEG * BH * DEPTH];
__device__ float g_qs[BH * DEPTH];

__device__ __forceinline__ float tf32r(float x) {
    float r;
    asm("cvt.rna.tf32.f32 %0, %1;" : "=f"(r) : "f"(x));
    return r;
}
__device__ __forceinline__ unsigned smem_u32(const void* p) {
    unsigned a;
    asm("{ .reg .u64 t; cvta.to.shared.u64 t, %1; cvt.u32.u64 %0, t; }"
        : "=r"(a) : "l"(p));
    return a;
}

// ---------------------------------------------------------------------------
// Weight transpose + tf32 rounding: Wt[n][k] = round_tf32(W[k][n])
// ---------------------------------------------------------------------------
__global__ void transpose_k(const float* __restrict__ W, float* __restrict__ Wt)
{
    __shared__ float t[32][33];
    const int bx = blockIdx.x * 32;   // n
    const int by = blockIdx.y * 32;   // k
    const int tx = threadIdx.x, ty = threadIdx.y;
#pragma unroll
    for (int i = 0; i < 32; i += 8)
        t[ty + i][tx] = W[(size_t)(by + ty + i) * DM + bx + tx];
    __syncthreads();
#pragma unroll
    for (int i = 0; i < 32; i += 8)
        Wt[(size_t)(bx + ty + i) * DM + by + tx] = tf32r(t[tx][ty + i]);
}

// ---------------------------------------------------------------------------
// tf32 mma.sync GEMM v2: C[M,1024] = A @ Wt^T + bias   (Wt is [N,K])
// CTA 128x128, 4 warps (2x2), warp tile 64x64 = 4x8 m16n8k8 tiles.
// k-chunk 8, 4-stage cp.async pipeline, smem stride 12 (conflict-free).
// grid (8, 128), 128 threads, 2 CTAs/SM.
// ---------------------------------------------------------------------------
#define SST 12          // floats per smem row (8 data + 4 pad), 48B (16B aligned)
#define STG 4
#define STAGEF (128 * SST)   // 1536 floats per stage per matrix

__device__ __forceinline__ void mma_tf32(float* d, const unsigned* a, const unsigned* b)
{
    asm volatile(
        "mma.sync.aligned.m16n8k8.row.col.f32.tf32.tf32.f32 "
        "{%0,%1,%2,%3}, {%4,%5,%6,%7}, {%8,%9}, {%0,%1,%2,%3};"
        : "+f"(d[0]), "+f"(d[1]), "+f"(d[2]), "+f"(d[3])
        : "r"(a[0]), "r"(a[1]), "r"(a[2]), "r"(a[3]), "r"(b[0]), "r"(b[1]));
}

__global__ __launch_bounds__(128, 2)
void gemm_mma2_k(const float* __restrict__ A, const float* __restrict__ Bt,
                 const float* __restrict__ bias, float* __restrict__ C, int act)
{
    __shared__ float As[STG][STAGEF];
    __shared__ float Bs[STG][STAGEF];

    const int tid = threadIdx.x;
    const int wid = tid >> 5, lane = tid & 31;
    const int gid = lane >> 2, tig = lane & 3;
    const int warpM = wid >> 1, warpN = wid & 1;
    const int bm = blockIdx.y * 128;
    const int bn = blockIdx.x * 128;

    // cp.async mapping: 2 xfers (16B) per thread per matrix per chunk
    const int r0l = tid >> 1;                 // j=0 row
    const int c0l = (tid & 1) * 4;            // col group
    const float* aL = A  + (size_t)(bm + r0l) * DM + c0l;
    const float* bL = Bt + (size_t)(bn + r0l) * DM + c0l;
    const unsigned sAd = smem_u32(&As[0][0]) + (r0l * SST + c0l) * 4;
    const unsigned sBd = smem_u32(&Bs[0][0]) + (r0l * SST + c0l) * 4;
    // second xfer: row + 64
    const float* aL2 = aL + (size_t)64 * DM;
    const float* bL2 = bL + (size_t)64 * DM;

    float acc[4][8][4];
#pragma unroll
    for (int i = 0; i < 4; ++i)
#pragma unroll
        for (int j = 0; j < 8; ++j)
#pragma unroll
            for (int q = 0; q < 4; ++q) acc[i][j][q] = 0.0f;

#define ISSUE_CHUNK(c)                                                          \
    do {                                                                        \
        const int _s = (c) & 3;                                                 \
        const int _k0 = (c) * 8;                                                \
        unsigned _da = sAd + _s * (STAGEF * 4);                                 \
        unsigned _db = sBd + _s * (STAGEF * 4);                                 \
        asm volatile("cp.async.ca.shared.global [%0], [%1], 16;"                \
                     :: "r"(_da), "l"(aL + _k0) : "memory");                    \
        asm volatile("cp.async.ca.shared.global [%0], [%1], 16;"                \
                     :: "r"(_da + 64 * SST * 4), "l"(aL2 + _k0) : "memory");    \
        asm volatile("cp.async.ca.shared.global [%0], [%1], 16;"                \
                     :: "r"(_db), "l"(bL + _k0) : "memory");                    \
        asm volatile("cp.async.ca.shared.global [%0], [%1], 16;"                \
                     :: "r"(_db + 64 * SST * 4), "l"(bL2 + _k0) : "memory");    \
    } while (0)

    ISSUE_CHUNK(0);
    asm volatile("cp.async.commit_group;" ::: "memory");
    ISSUE_CHUNK(1);
    asm volatile("cp.async.commit_group;" ::: "memory");
    ISSUE_CHUNK(2);
    asm volatile("cp.async.commit_group;" ::: "memory");

    for (int c = 0; c < 128; ++c) {
        asm volatile("cp.async.wait_group 2;" ::: "memory");
        __syncthreads();
        if (c + 3 < 128) ISSUE_CHUNK(c + 3);
        asm volatile("cp.async.commit_group;" ::: "memory");

        const float* sa = As[c & 3];
        const float* sb = Bs[c & 3];
        unsigned afr[4][4], bfr[8][2];
#pragma unroll
        for (int mt = 0; mt < 4; ++mt) {
            const float* p = sa + (warpM * 64 + mt * 16 + gid) * SST + tig;
            afr[mt][0] = __float_as_uint(p[0]);
            afr[mt][1] = __float_as_uint(p[8 * SST]);
            afr[mt][2] = __float_as_uint(p[4]);
            afr[mt][3] = __float_as_uint(p[8 * SST + 4]);
        }
#pragma unroll
        for (int nt = 0; nt < 8; ++nt) {
            const float* p = sb + (warpN * 64 + nt * 8 + gid) * SST + tig;
            bfr[nt][0] = __float_as_uint(p[0]);
            bfr[nt][1] = __float_as_uint(p[4]);
        }
#pragma unroll
        for (int mt = 0; mt < 4; ++mt)
#pragma unroll
            for (int nt = 0; nt < 8; ++nt)
                mma_tf32(acc[mt][nt], afr[mt], bfr[nt]);
        __syncthreads();
    }

    // epilogue
#pragma unroll
    for (int mt = 0; mt < 4; ++mt) {
        const int r = bm + warpM * 64 + mt * 16 + gid;
#pragma unroll
        for (int nt = 0; nt < 8; ++nt) {
            const int cn = bn + warpN * 64 + nt * 8 + 2 * tig;
            const float b0 = bias[cn], b1 = bias[cn + 1];
            float v0 = acc[mt][nt][0] + b0;
            float v1 = acc[mt][nt][1] + b1;
            float v2 = acc[mt][nt][2] + b0;
            float v3 = acc[mt][nt][3] + b1;
            if (act == 1) {
                v0 = (v0 > 0.0f) ? (v0 + 1.0f) : expf(v0);
                v1 = (v1 > 0.0f) ? (v1 + 1.0f) : expf(v1);
                v2 = (v2 > 0.0f) ? (v2 + 1.0f) : expf(v2);
                v3 = (v3 > 0.0f) ? (v3 + 1.0f) : expf(v3);
            }
            *(float2*)&C[(size_t)r * DM + cn] = make_float2(v0, v1);
            *(float2*)&C[(size_t)(r + 8) * DM + cn] = make_float2(v2, v3);
        }
    }
}

// ---------------------------------------------------------------------------
// Per-(b,h) KtQ[d][e] = sum_l K[l,d]*Q[l,e] and qsum[e] = sum_l Q[l,e]
// ---------------------------------------------------------------------------
__global__ __launch_bounds__(256)
void ktq_k()
{
    __shared__ float Ks[16][64];
    __shared__ float Qs[16][64];

    const int bh = blockIdx.x;
    const int b = bh >> 4, h = bh & 15;
    const int seg = blockIdx.y;
    const int tid = threadIdx.x;
    const int tx = tid & 15;
    const int ty = tid >> 4;
    const int ldrow = tid >> 4;
    const int ldc4  = (tid & 15) * 4;

    float acc[4][4];
#pragma unroll
    for (int i = 0; i < 4; ++i)
#pragma unroll
        for (int j = 0; j < 4; ++j) acc[i][j] = 0.0f;
    float qsv = 0.0f;

    const size_t hb = (size_t)h * DEPTH;

    for (int ch = 0; ch < SEG_ROWS / 16; ++ch) {
        int n0 = seg * SEG_ROWS + ch * 16;
        size_t gbase = ((size_t)(b * Nn + n0 + ldrow)) * DM + hb + ldc4;
        *(float4*)&Ks[ldrow][ldc4] = *(const float4*)&g_K[gbase];
        *(float4*)&Qs[ldrow][ldc4] = *(const float4*)&g_Q[gbase];
        __syncthreads();

#pragma unroll
        for (int l = 0; l < 16; ++l) {
            float ra[4], rb[4];
            *(float4*)ra = *(const float4*)&Ks[l][ty * 4];
            *(float4*)rb = *(const float4*)&Qs[l][tx * 4];
#pragma unroll
            for (int i = 0; i < 4; ++i)
#pragma unroll
                for (int j = 0; j < 4; ++j)
                    acc[i][j] = fmaf(ra[i], rb[j], acc[i][j]);
        }
        if (tid < 64) {
#pragma unroll
            for (int l = 0; l < 16; ++l) qsv += Qs[l][tid];
        }
        __syncthreads();
    }

    float* outp = &g_KtQp[((size_t)seg * BH + bh) * (DEPTH * DEPTH)];
#pragma unroll
    for (int i = 0; i < 4; ++i)
#pragma unroll
        for (int j = 0; j < 4; ++j)
            outp[(ty * 4 + i) * DEPTH + tx * 4 + j] = acc[i][j];

    if (tid < 64)
        g_qsp[((size_t)seg * BH + bh) * DEPTH + tid] = qsv;
}

__global__ void red_ktq_k()
{
    int i = blockIdx.x * 256 + threadIdx.x;
    if (i < BH * DEPTH * DEPTH) {
        float s = 0.0f;
#pragma unroll
        for (int seg = 0; seg < NSEG; ++seg)
            s += g_KtQp[seg * (BH * DEPTH * DEPTH) + i];
        g_KtQ[i] = s;
    }
}
__global__ void red_qs_k()
{
    int i = blockIdx.x * 256 + threadIdx.x;
    if (i < BH * DEPTH) {
        float s = 0.0f;
#pragma unroll
        for (int seg = 0; seg < NSEG; ++seg)
            s += g_qsp[seg * (BH * DEPTH) + i];
        g_qs[i] = s;
    }
}

// ---------------------------------------------------------------------------
// out[m,e] = (sum_d V[m,d]*KtQ[d,e]) / (K[m,:].qsum + 1e-9)
// ---------------------------------------------------------------------------
__global__ __launch_bounds__(512)
void out_k()
{
    __shared__ float S[DEPTH * DEPTH];
    __shared__ float qs[DEPTH];
    __shared__ float Vs[8][DEPTH];
    __shared__ float Ks2[8][DEPTH];

    const int bh = blockIdx.x;
    const int b = bh >> 4, h = bh & 15;
    const int rowbase = blockIdx.y * 64;
    const int tx = threadIdx.x;
    const int ty = threadIdx.y;
    const int tid = ty * 64 + tx;

#pragma unroll
    for (int p = 0; p < 8; ++p)
        S[tid + p * 512] = g_KtQ[(size_t)bh * (DEPTH * DEPTH) + tid + p * 512];
    if (tid < DEPTH) qs[tid] = g_qs[(size_t)bh * DEPTH + tid];
    __syncthreads();

    const size_t hb = (size_t)h * DEPTH;

    for (int it = 0; it < 8; ++it) {
        int row = rowbase + it * 8 + ty;
        size_t base = ((size_t)(b * Nn + row)) * DM + hb;
        Vs[ty][tx]  = g_V[base + tx];
        Ks2[ty][tx] = g_K[base + tx];
        __syncthreads();

        float z = 0.0f;
#pragma unroll
        for (int d = 0; d < DEPTH; ++d) z = fmaf(Ks2[ty][d], qs[d], z);
        float o = 0.0f;
#pragma unroll
        for (int d = 0; d < DEPTH; ++d) o = fmaf(Vs[ty][d], S[d * DEPTH + tx], o);

        g_attn[base + tx] = o / (z + 1e-9f);
        __syncthreads();
    }
}

// ---------------------------------------------------------------------------
// x = query + proj; LayerNorm(x)*gamma + beta
// ---------------------------------------------------------------------------
__global__ __launch_bounds__(256)
void ln_k(const float* __restrict__ resid, const float* __restrict__ gamma,
          const float* __restrict__ beta, float* __restrict__ out)
{
    __shared__ float red[256];
    const int row = blockIdx.x;
    const int tid = threadIdx.x;
    const float* a = g_proj + (size_t)row * DM;
    const float* r = resid + (size_t)row * DM;

    float x[4];
    float s = 0.0f;
#pragma unroll
    for (int j = 0; j < 4; ++j) {
        int c = tid + j * 256;
        x[j] = a[c] + r[c];
        s += x[j];
    }
    red[tid] = s;
    __syncthreads();
    for (int st = 128; st > 0; st >>= 1) {
        if (tid < st) red[tid] += red[tid + st];
        __syncthreads();
    }
    float mu = red[0] * (1.0f / 1024.0f);
    __syncthreads();

    float v = 0.0f;
#pragma unroll
    for (int j = 0; j < 4; ++j) {
        float d = x[j] - mu;
        v += d * d;
    }
    red[tid] = v;
    __syncthreads();
    for (int st = 128; st > 0; st >>= 1) {
        if (tid < st) red[tid] += red[tid + st];
        __syncthreads();
    }
    float inv = rsqrtf(red[0] * (1.0f / 1024.0f) + 1e-6f);

    float* o = out + (size_t)row * DM;
#pragma unroll
    for (int j = 0; j < 4; ++j) {
        int c = tid + j * 256;
        o[c] = (x[j] - mu) * inv * gamma[c] + beta[c];
    }
}

// ---------------------------------------------------------------------------
// Launch
// ---------------------------------------------------------------------------
extern "C" void kernel_launch(void* const* d_in, const int* in_sizes, int n_in,
                              void* d_out, int out_size)
{
    const float* query = (const float*)d_in[0];
    const float* key_  = (const float*)d_in[1];
    const float* value = (const float*)d_in[2];
    const float* Wq = (const float*)d_in[3];
    const float* bq = (const float*)d_in[4];
    const float* Wk = (const float*)d_in[5];
    const float* bk = (const float*)d_in[6];
    const float* Wv = (const float*)d_in[7];
    const float* bv = (const float*)d_in[8];
    const float* Wo = (const float*)d_in[9];
    const float* bo = (const float*)d_in[10];
    const float* gamma = (const float*)d_in[11];
    const float* beta  = (const float*)d_in[12];
    float* out = (float*)d_out;

    void *pQ, *pK, *pV, *pAttn, *pProj, *pWt;
    cudaGetSymbolAddress(&pQ, g_Q);
    cudaGetSymbolAddress(&pK, g_K);
    cudaGetSymbolAddress(&pV, g_V);
    cudaGetSymbolAddress(&pAttn, g_attn);
    cudaGetSymbolAddress(&pProj, g_proj);
    cudaGetSymbolAddress(&pWt, g_Wt);
    float* Wt = (float*)pWt;

    // Transpose + tf32-round the 4 weight matrices
    dim3 tgrid(DM / 32, DM / 32), tblk(32, 8);
    transpose_k<<<tgrid, tblk>>>(Wq, Wt + 0 * DM * DM);
    transpose_k<<<tgrid, tblk>>>(Wk, Wt + 1 * DM * DM);
    transpose_k<<<tgrid, tblk>>>(Wv, Wt + 2 * DM * DM);
    transpose_k<<<tgrid, tblk>>>(Wo, Wt + 3 * DM * DM);

    dim3 ggrid(DM / 128, ROWS / 128);

    gemm_mma2_k<<<ggrid, 128>>>(query, Wt + 0 * DM * DM, bq, (float*)pQ, 1);
    gemm_mma2_k<<<ggrid, 128>>>(key_,  Wt + 1 * DM * DM, bk, (float*)pK, 1);
    gemm_mma2_k<<<ggrid, 128>>>(value, Wt + 2 * DM * DM, bv, (float*)pV, 0);

    ktq_k<<<dim3(BH, NSEG), 256>>>();
    red_ktq_k<<<(BH * DEPTH * DEPTH + 255) / 256, 256>>>();
    red_qs_k<<<(BH * DEPTH + 255) / 256, 256>>>();

    out_k<<<dim3(BH, Nn / 64), dim3(64, 8)>>>();

    gemm_mma2_k<<<ggrid, 128>>>((const float*)pAttn, Wt + 3 * DM * DM, bo, (float*)pProj, 0);

    ln_k<<<ROWS, 256>>>(query, gamma, beta, out);
}

// round 5
// speedup vs baseline: 2.6699x; 1.1383x over previous
#include <cuda_runtime.h>
#include <cuda_bf16.h>
#include <math.h>

// Problem constants
#define Bz 4
#define Nn 4096
#define DM 1024
#define Hh 16
#define DEPTH 64
#define ROWS (Bz * Nn)          // 16384
#define BH (Bz * Hh)            // 64
#define NSEG 16
#define SEG_ROWS (Nn / NSEG)    // 256

// ---------------------------------------------------------------------------
// Scratch (device globals)
// ---------------------------------------------------------------------------
__device__ float g_Q[ROWS * DM];
__device__ float g_K[ROWS * DM];
__device__ float g_V[ROWS * DM];
__device__ float g_attn[ROWS * DM];
__device__ float g_proj[ROWS * DM];
__device__ float g_Wt[4 * DM * DM];
__device__ float g_KtQp[NSEG * BH * DEPTH * DEPTH];
__device__ float g_KtQ[BH * DEPTH * DEPTH];
__device__ float g_qsp[NSEG * BH * DEPTH];
__device__ float g_qs[BH * DEPTH];

__device__ __forceinline__ float tf32r(float x) {
    float r;
    asm("cvt.rna.tf32.f32 %0, %1;" : "=f"(r) : "f"(x));
    return r;
}
__device__ __forceinline__ unsigned smem_u32(const void* p) {
    unsigned a;
    asm("{ .reg .u64 t; cvta.to.shared.u64 t, %1; cvt.u32.u64 %0, t; }"
        : "=r"(a) : "l"(p));
    return a;
}

// ---------------------------------------------------------------------------
// Weight transpose + tf32 rounding, all 4 matrices in one launch (z = which)
// ---------------------------------------------------------------------------
__global__ void transpose_k(const float* __restrict__ W0, const float* __restrict__ W1,
                            const float* __restrict__ W2, const float* __restrict__ W3,
                            float* __restrict__ Wt)
{
    __shared__ float t[32][33];
    const int m = blockIdx.z;
    const float* W = (m == 0) ? W0 : (m == 1) ? W1 : (m == 2) ? W2 : W3;
    float* dst = Wt + (size_t)m * DM * DM;
    const int bx = blockIdx.x * 32;   // n
    const int by = blockIdx.y * 32;   // k
    const int tx = threadIdx.x, ty = threadIdx.y;
#pragma unroll
    for (int i = 0; i < 32; i += 8)
        t[ty + i][tx] = W[(size_t)(by + ty + i) * DM + bx + tx];
    __syncthreads();
#pragma unroll
    for (int i = 0; i < 32; i += 8)
        dst[(size_t)(bx + ty + i) * DM + by + tx] = tf32r(t[tx][ty + i]);
}

// ---------------------------------------------------------------------------
// tf32 mma.sync GEMM (unchanged from R4 — at the legacy-HMMA ceiling)
// ---------------------------------------------------------------------------
#define SST 12
#define STG 4
#define STAGEF (128 * SST)

__device__ __forceinline__ void mma_tf32(float* d, const unsigned* a, const unsigned* b)
{
    asm volatile(
        "mma.sync.aligned.m16n8k8.row.col.f32.tf32.tf32.f32 "
        "{%0,%1,%2,%3}, {%4,%5,%6,%7}, {%8,%9}, {%0,%1,%2,%3};"
        : "+f"(d[0]), "+f"(d[1]), "+f"(d[2]), "+f"(d[3])
        : "r"(a[0]), "r"(a[1]), "r"(a[2]), "r"(a[3]), "r"(b[0]), "r"(b[1]));
}

__global__ __launch_bounds__(128, 2)
void gemm_mma2_k(const float* __restrict__ A, const float* __restrict__ Bt,
                 const float* __restrict__ bias, float* __restrict__ C, int act)
{
    __shared__ float As[STG][STAGEF];
    __shared__ float Bs[STG][STAGEF];

    const int tid = threadIdx.x;
    const int wid = tid >> 5, lane = tid & 31;
    const int gid = lane >> 2, tig = lane & 3;
    const int warpM = wid >> 1, warpN = wid & 1;
    const int bm = blockIdx.y * 128;
    const int bn = blockIdx.x * 128;

    const int r0l = tid >> 1;
    const int c0l = (tid & 1) * 4;
    const float* aL = A  + (size_t)(bm + r0l) * DM + c0l;
    const float* bL = Bt + (size_t)(bn + r0l) * DM + c0l;
    const unsigned sAd = smem_u32(&As[0][0]) + (r0l * SST + c0l) * 4;
    const unsigned sBd = smem_u32(&Bs[0][0]) + (r0l * SST + c0l) * 4;
    const float* aL2 = aL + (size_t)64 * DM;
    const float* bL2 = bL + (size_t)64 * DM;

    float acc[4][8][4];
#pragma unroll
    for (int i = 0; i < 4; ++i)
#pragma unroll
        for (int j = 0; j < 8; ++j)
#pragma unroll
            for (int q = 0; q < 4; ++q) acc[i][j][q] = 0.0f;

#define ISSUE_CHUNK(c)                                                          \
    do {                                                                        \
        const int _s = (c) & 3;                                                 \
        const int _k0 = (c) * 8;                                                \
        unsigned _da = sAd + _s * (STAGEF * 4);                                 \
        unsigned _db = sBd + _s * (STAGEF * 4);                                 \
        asm volatile("cp.async.ca.shared.global [%0], [%1], 16;"                \
                     :: "r"(_da), "l"(aL + _k0) : "memory");                    \
        asm volatile("cp.async.ca.shared.global [%0], [%1], 16;"                \
                     :: "r"(_da + 64 * SST * 4), "l"(aL2 + _k0) : "memory");    \
        asm volatile("cp.async.ca.shared.global [%0], [%1], 16;"                \
                     :: "r"(_db), "l"(bL + _k0) : "memory");                    \
        asm volatile("cp.async.ca.shared.global [%0], [%1], 16;"                \
                     :: "r"(_db + 64 * SST * 4), "l"(bL2 + _k0) : "memory");    \
    } while (0)

    ISSUE_CHUNK(0);
    asm volatile("cp.async.commit_group;" ::: "memory");
    ISSUE_CHUNK(1);
    asm volatile("cp.async.commit_group;" ::: "memory");
    ISSUE_CHUNK(2);
    asm volatile("cp.async.commit_group;" ::: "memory");

    for (int c = 0; c < 128; ++c) {
        asm volatile("cp.async.wait_group 2;" ::: "memory");
        __syncthreads();
        if (c + 3 < 128) ISSUE_CHUNK(c + 3);
        asm volatile("cp.async.commit_group;" ::: "memory");

        const float* sa = As[c & 3];
        const float* sb = Bs[c & 3];
        unsigned afr[4][4], bfr[8][2];
#pragma unroll
        for (int mt = 0; mt < 4; ++mt) {
            const float* p = sa + (warpM * 64 + mt * 16 + gid) * SST + tig;
            afr[mt][0] = __float_as_uint(p[0]);
            afr[mt][1] = __float_as_uint(p[8 * SST]);
            afr[mt][2] = __float_as_uint(p[4]);
            afr[mt][3] = __float_as_uint(p[8 * SST + 4]);
        }
#pragma unroll
        for (int nt = 0; nt < 8; ++nt) {
            const float* p = sb + (warpN * 64 + nt * 8 + gid) * SST + tig;
            bfr[nt][0] = __float_as_uint(p[0]);
            bfr[nt][1] = __float_as_uint(p[4]);
        }
#pragma unroll
        for (int mt = 0; mt < 4; ++mt)
#pragma unroll
            for (int nt = 0; nt < 8; ++nt)
                mma_tf32(acc[mt][nt], afr[mt], bfr[nt]);
        __syncthreads();
    }

#pragma unroll
    for (int mt = 0; mt < 4; ++mt) {
        const int r = bm + warpM * 64 + mt * 16 + gid;
#pragma unroll
        for (int nt = 0; nt < 8; ++nt) {
            const int cn = bn + warpN * 64 + nt * 8 + 2 * tig;
            const float b0 = bias[cn], b1 = bias[cn + 1];
            float v0 = acc[mt][nt][0] + b0;
            float v1 = acc[mt][nt][1] + b1;
            float v2 = acc[mt][nt][2] + b0;
            float v3 = acc[mt][nt][3] + b1;
            if (act == 1) {
                v0 = (v0 > 0.0f) ? (v0 + 1.0f) : expf(v0);
                v1 = (v1 > 0.0f) ? (v1 + 1.0f) : expf(v1);
                v2 = (v2 > 0.0f) ? (v2 + 1.0f) : expf(v2);
                v3 = (v3 > 0.0f) ? (v3 + 1.0f) : expf(v3);
            }
            *(float2*)&C[(size_t)r * DM + cn] = make_float2(v0, v1);
            *(float2*)&C[(size_t)(r + 8) * DM + cn] = make_float2(v2, v3);
        }
    }
}

// ---------------------------------------------------------------------------
// ktq v2: double-buffered smem, register prefetch, one sync per chunk.
// grid (BH, NSEG), 256 threads.
// ---------------------------------------------------------------------------
__global__ __launch_bounds__(256)
void ktq_k()
{
    __shared__ float Ks[2][16][64];
    __shared__ float Qs[2][16][64];

    const int bh = blockIdx.x;
    const int b = bh >> 4, h = bh & 15;
    const int seg = blockIdx.y;
    const int tid = threadIdx.x;
    const int tx = tid & 15;
    const int ty = tid >> 4;
    const int ldrow = tid >> 4;
    const int ldc4  = (tid & 15) * 4;

    float acc[4][4];
#pragma unroll
    for (int i = 0; i < 4; ++i)
#pragma unroll
        for (int j = 0; j < 4; ++j) acc[i][j] = 0.0f;
    float qsv = 0.0f;

    const size_t hb = (size_t)h * DEPTH;
    const int nchunk = SEG_ROWS / 16;   // 16

    size_t gbase = ((size_t)(b * Nn + seg * SEG_ROWS + ldrow)) * DM + hb + ldc4;
    float4 ka = *(const float4*)&g_K[gbase];
    float4 qa = *(const float4*)&g_Q[gbase];

    for (int ch = 0; ch < nchunk; ++ch) {
        const int s = ch & 1;
        *(float4*)&Ks[s][ldrow][ldc4] = ka;
        *(float4*)&Qs[s][ldrow][ldc4] = qa;
        __syncthreads();
        if (ch + 1 < nchunk) {
            size_t gn = gbase + (size_t)(ch + 1) * 16 * DM;
            ka = *(const float4*)&g_K[gn];
            qa = *(const float4*)&g_Q[gn];
        }
#pragma unroll
        for (int l = 0; l < 16; ++l) {
            float ra[4], rb[4];
            *(float4*)ra = *(const float4*)&Ks[s][l][ty * 4];
            *(float4*)rb = *(const float4*)&Qs[s][l][tx * 4];
#pragma unroll
            for (int i = 0; i < 4; ++i)
#pragma unroll
                for (int j = 0; j < 4; ++j)
                    acc[i][j] = fmaf(ra[i], rb[j], acc[i][j]);
        }
        if (tid < 64) {
#pragma unroll
            for (int l = 0; l < 16; ++l) qsv += Qs[s][l][tid];
        }
    }

    float* outp = &g_KtQp[((size_t)seg * BH + bh) * (DEPTH * DEPTH)];
#pragma unroll
    for (int i = 0; i < 4; ++i)
#pragma unroll
        for (int j = 0; j < 4; ++j)
            outp[(ty * 4 + i) * DEPTH + tx * 4 + j] = acc[i][j];

    if (tid < 64)
        g_qsp[((size_t)seg * BH + bh) * DEPTH + tid] = qsv;
}

// Merged deterministic reduction (KtQ partials + qsum partials)
__global__ void red_k()
{
    int i = blockIdx.x * 256 + threadIdx.x;
    if (i < BH * DEPTH * DEPTH) {
        float s = 0.0f;
#pragma unroll
        for (int seg = 0; seg < NSEG; ++seg)
            s += g_KtQp[seg * (BH * DEPTH * DEPTH) + i];
        g_KtQ[i] = s;
    } else {
        int j = i - BH * DEPTH * DEPTH;
        if (j < BH * DEPTH) {
            float s = 0.0f;
#pragma unroll
            for (int seg = 0; seg < NSEG; ++seg)
                s += g_qsp[seg * (BH * DEPTH) + j];
            g_qs[j] = s;
        }
    }
}

// ---------------------------------------------------------------------------
// out v2: warp-per-row, no block syncs in main loop.
// grid (BH, Nn/64), 256 threads (8 warps x 8 rows each).
// ---------------------------------------------------------------------------
__global__ __launch_bounds__(256)
void out_k()
{
    __shared__ float S[DEPTH * DEPTH];
    __shared__ float qs[DEPTH];
    __shared__ float Vs[8][DEPTH];

    const int bh = blockIdx.x;
    const int b = bh >> 4, h = bh & 15;
    const int rowbase = blockIdx.y * 64;
    const int tid = threadIdx.x;
    const int w = tid >> 5, lane = tid & 31;

    {
        const float4* src = (const float4*)&g_KtQ[(size_t)bh * (DEPTH * DEPTH)];
#pragma unroll
        for (int p = 0; p < 4; ++p)
            ((float4*)S)[tid + p * 256] = src[tid + p * 256];
        if (tid < DEPTH) qs[tid] = g_qs[(size_t)bh * DEPTH + tid];
    }
    __syncthreads();

    const size_t hb = (size_t)h * DEPTH;
    const float q0 = qs[lane * 2], q1 = qs[lane * 2 + 1];

    for (int it = 0; it < 8; ++it) {
        const int row = rowbase + it * 8 + w;
        const size_t base = ((size_t)(b * Nn + row)) * DM + hb;
        float2 kv = *(const float2*)&g_K[base + lane * 2];
        float2 vv = *(const float2*)&g_V[base + lane * 2];
        *(float2*)&Vs[w][lane * 2] = vv;
        float zp = kv.x * q0 + kv.y * q1;
#pragma unroll
        for (int o = 16; o > 0; o >>= 1)
            zp += __shfl_xor_sync(0xFFFFFFFFu, zp, o);
        __syncwarp();

        float o0 = 0.0f, o1 = 0.0f;
#pragma unroll
        for (int g = 0; g < 16; ++g) {
            float4 v = *(const float4*)&Vs[w][g * 4];
            const float* s0 = &S[(g * 4) * DEPTH + lane];
            o0 = fmaf(v.x, s0[0 * DEPTH], o0);
            o0 = fmaf(v.y, s0[1 * DEPTH], o0);
            o0 = fmaf(v.z, s0[2 * DEPTH], o0);
            o0 = fmaf(v.w, s0[3 * DEPTH], o0);
            const float* s1 = s0 + 32;
            o1 = fmaf(v.x, s1[0 * DEPTH], o1);
            o1 = fmaf(v.y, s1[1 * DEPTH], o1);
            o1 = fmaf(v.z, s1[2 * DEPTH], o1);
            o1 = fmaf(v.w, s1[3 * DEPTH], o1);
        }
        const float inv = 1.0f / (zp + 1e-9f);
        g_attn[base + lane]      = o0 * inv;
        g_attn[base + lane + 32] = o1 * inv;
        __syncwarp();
    }
}

// ---------------------------------------------------------------------------
// ln v2: warp-shuffle reductions, float4 I/O. One block (256) per row.
// ---------------------------------------------------------------------------
__global__ __launch_bounds__(256)
void ln_k(const float* __restrict__ resid, const float* __restrict__ gamma,
          const float* __restrict__ beta, float* __restrict__ out)
{
    __shared__ float ws[8];
    const int row = blockIdx.x;
    const int tid = threadIdx.x;
    const int wid = tid >> 5, lane = tid & 31;

    float4 a = *(const float4*)&g_proj[(size_t)row * DM + tid * 4];
    float4 r = *(const float4*)&resid[(size_t)row * DM + tid * 4];
    float4 x = make_float4(a.x + r.x, a.y + r.y, a.z + r.z, a.w + r.w);

    float s = x.x + x.y + x.z + x.w;
#pragma unroll
    for (int o = 16; o > 0; o >>= 1) s += __shfl_xor_sync(0xFFFFFFFFu, s, o);
    if (lane == 0) ws[wid] = s;
    __syncthreads();
    if (tid < 32) {
        float t = (lane < 8) ? ws[lane] : 0.0f;
#pragma unroll
        for (int o = 4; o > 0; o >>= 1) t += __shfl_xor_sync(0xFFFFFFFFu, t, o);
        if (lane == 0) ws[0] = t;
    }
    __syncthreads();
    const float mu = ws[0] * (1.0f / 1024.0f);
    __syncthreads();

    float dx = x.x - mu, dy = x.y - mu, dz = x.z - mu, dw = x.w - mu;
    float v = dx * dx + dy * dy + dz * dz + dw * dw;
#pragma unroll
    for (int o = 16; o > 0; o >>= 1) v += __shfl_xor_sync(0xFFFFFFFFu, v, o);
    if (lane == 0) ws[wid] = v;
    __syncthreads();
    if (tid < 32) {
        float t = (lane < 8) ? ws[lane] : 0.0f;
#pragma unroll
        for (int o = 4; o > 0; o >>= 1) t += __shfl_xor_sync(0xFFFFFFFFu, t, o);
        if (lane == 0) ws[0] = t;
    }
    __syncthreads();
    const float inv = rsqrtf(ws[0] * (1.0f / 1024.0f) + 1e-6f);

    float4 gm = *(const float4*)&gamma[tid * 4];
    float4 bt = *(const float4*)&beta[tid * 4];
    float4 o;
    o.x = dx * inv * gm.x + bt.x;
    o.y = dy * inv * gm.y + bt.y;
    o.z = dz * inv * gm.z + bt.z;
    o.w = dw * inv * gm.w + bt.w;
    *(float4*)&out[(size_t)row * DM + tid * 4] = o;
}

// ---------------------------------------------------------------------------
// Launch
// ---------------------------------------------------------------------------
extern "C" void kernel_launch(void* const* d_in, const int* in_sizes, int n_in,
                              void* d_out, int out_size)
{
    const float* query = (const float*)d_in[0];
    const float* key_  = (const float*)d_in[1];
    const float* value = (const float*)d_in[2];
    const float* Wq = (const float*)d_in[3];
    const float* bq = (const float*)d_in[4];
    const float* Wk = (const float*)d_in[5];
    const float* bk = (const float*)d_in[6];
    const float* Wv = (const float*)d_in[7];
    const float* bv = (const float*)d_in[8];
    const float* Wo = (const float*)d_in[9];
    const float* bo = (const float*)d_in[10];
    const float* gamma = (const float*)d_in[11];
    const float* beta  = (const float*)d_in[12];
    float* out = (float*)d_out;

    void *pQ, *pK, *pV, *pAttn, *pProj, *pWt;
    cudaGetSymbolAddress(&pQ, g_Q);
    cudaGetSymbolAddress(&pK, g_K);
    cudaGetSymbolAddress(&pV, g_V);
    cudaGetSymbolAddress(&pAttn, g_attn);
    cudaGetSymbolAddress(&pProj, g_proj);
    cudaGetSymbolAddress(&pWt, g_Wt);
    float* Wt = (float*)pWt;

    transpose_k<<<dim3(DM / 32, DM / 32, 4), dim3(32, 8)>>>(Wq, Wk, Wv, Wo, Wt);

    dim3 ggrid(DM / 128, ROWS / 128);

    gemm_mma2_k<<<ggrid, 128>>>(query, Wt + 0 * DM * DM, bq, (float*)pQ, 1);
    gemm_mma2_k<<<ggrid, 128>>>(key_,  Wt + 1 * DM * DM, bk, (float*)pK, 1);
    gemm_mma2_k<<<ggrid, 128>>>(value, Wt + 2 * DM * DM, bv, (float*)pV, 0);

    ktq_k<<<dim3(BH, NSEG), 256>>>();
    red_k<<<(BH * DEPTH * DEPTH + BH * DEPTH + 255) / 256, 256>>>();

    out_k<<<dim3(BH, Nn / 64), 256>>>();

    gemm_mma2_k<<<ggrid, 128>>>((const float*)pAttn, Wt + 3 * DM * DM, bo, (float*)pProj, 0);

    ln_k<<<ROWS, 256>>>(query, gamma, beta, out);
}